// round 1
// baseline (speedup 1.0000x reference)
#include <cuda_runtime.h>
#include <math.h>

#define BATCH 8
#define TLEN  2048
#define DIM   1024
#define HID   4096
#define BT    (BATCH*TLEN)

// ---------------- scratch (device globals; allocation-free) ----------------
__device__ float g_xn  [(size_t)BT*DIM];
__device__ float g_q   [(size_t)BT*DIM];
__device__ float g_k   [(size_t)BT*DIM];
__device__ float g_v   [(size_t)BT*DIM];
__device__ float g_sc  [(size_t)BATCH*TLEN*TLEN];
__device__ float g_attn[(size_t)BT*DIM];
__device__ float g_x1  [(size_t)BT*DIM];
__device__ float g_h   [(size_t)BT*DIM];
__device__ float g_h1  [(size_t)BT*HID];

// ---------------- RMSNorm ----------------
__global__ void rmsnorm_kernel(const float* __restrict__ x,
                               const float* __restrict__ w,
                               float* __restrict__ o) {
    int row = blockIdx.x;
    int tid = threadIdx.x;              // 256 threads, 4 floats each = 1024
    const float4* xr = (const float4*)(x + (size_t)row * DIM);
    float4 v = xr[tid];
    float ss = v.x*v.x + v.y*v.y + v.z*v.z + v.w*v.w;
    #pragma unroll
    for (int off = 16; off; off >>= 1) ss += __shfl_xor_sync(~0u, ss, off);
    __shared__ float red[8];
    if ((tid & 31) == 0) red[tid >> 5] = ss;
    __syncthreads();
    float tot = 0.f;
    #pragma unroll
    for (int i = 0; i < 8; i++) tot += red[i];
    float inv = rsqrtf(tot * (1.0f/DIM) + 1e-6f);
    float4 w4 = ((const float4*)w)[tid];
    float4 r;
    r.x = v.x * inv * w4.x; r.y = v.y * inv * w4.y;
    r.z = v.z * inv * w4.z; r.w = v.w * inv * w4.w;
    ((float4*)(o + (size_t)row * DIM))[tid] = r;
}

// ---------------- causal softmax (in-place, row length TLEN) ----------------
__global__ void softmax_causal_kernel(float* __restrict__ s) {
    int t = blockIdx.x;
    int b = blockIdx.y;
    float* row = s + ((size_t)b * TLEN + t) * TLEN;
    int tid = threadIdx.x;              // 256 threads, 8 elems each
    int nvalid = t + 1;
    float vals[8];
    float mx = -3.0e38f;
    #pragma unroll
    for (int i = 0; i < 8; i++) {
        int idx = tid + i * 256;
        vals[i] = (idx < nvalid) ? row[idx] : -3.0e38f;
        mx = fmaxf(mx, vals[i]);
    }
    __shared__ float red[8];
    #pragma unroll
    for (int off = 16; off; off >>= 1) mx = fmaxf(mx, __shfl_xor_sync(~0u, mx, off));
    if ((tid & 31) == 0) red[tid >> 5] = mx;
    __syncthreads();
    mx = -3.0e38f;
    #pragma unroll
    for (int i = 0; i < 8; i++) mx = fmaxf(mx, red[i]);

    float sum = 0.f;
    #pragma unroll
    for (int i = 0; i < 8; i++) {
        int idx = tid + i * 256;
        vals[i] = (idx < nvalid) ? __expf(vals[i] - mx) : 0.f;
        sum += vals[i];
    }
    #pragma unroll
    for (int off = 16; off; off >>= 1) sum += __shfl_xor_sync(~0u, sum, off);
    __syncthreads();   // all reads of red done
    if ((tid & 31) == 0) red[tid >> 5] = sum;
    __syncthreads();
    float tot = 0.f;
    #pragma unroll
    for (int i = 0; i < 8; i++) tot += red[i];
    float inv = 1.0f / tot;
    #pragma unroll
    for (int i = 0; i < 8; i++) {
        int idx = tid + i * 256;
        row[idx] = vals[i] * inv;
    }
}

// ---------------- SGEMM: C = alpha*(A @ B[^T]) [+bias] [gelu] [+res] ----------
// BM=BN=128, BK=16, 256 threads, 8x8 per thread. All dims multiples of 128/16.
template<bool TB, bool GELU>
__global__ void __launch_bounds__(256, 2) sgemm_kernel(
    const float* __restrict__ A, const float* __restrict__ B, float* __restrict__ C,
    int M, int N, int K,
    long sA, long sB, long sC,
    float alpha,
    const float* __restrict__ bias,
    const float* __restrict__ res)
{
    __shared__ float As[16][132];
    __shared__ float Bs[16][132];

    int bn = blockIdx.x, bm = blockIdx.y, bz = blockIdx.z;
    const float* Ab = A + (long)bz * sA + (long)bm * 128 * K;
    const float* Bb = TB ? (B + (long)bz * sB + (long)bn * 128 * K)
                         : (B + (long)bz * sB + (long)bn * 128);
    float* Cb = C + (long)bz * sC + (long)bm * 128 * N + bn * 128;
    const float* Rb = res ? (res + (long)bz * sC + (long)bm * 128 * N + bn * 128) : nullptr;

    int tid = threadIdx.x;
    int tx = tid & 15;     // col group
    int ty = tid >> 4;     // row group

    float acc[8][8];
    #pragma unroll
    for (int i = 0; i < 8; i++)
        #pragma unroll
        for (int j = 0; j < 8; j++) acc[i][j] = 0.f;

    int arow = tid >> 2;          // 0..63
    int acol = (tid & 3) * 4;     // 0,4,8,12
    int brow = tid >> 5;          // 0..7   (NN path)
    int bcol = (tid & 31) * 4;    // 0..124 (NN path)

    for (int k0 = 0; k0 < K; k0 += 16) {
        float4 a0 = *(const float4*)(Ab + (long)arow * K + k0 + acol);
        float4 a1 = *(const float4*)(Ab + (long)(arow + 64) * K + k0 + acol);
        As[acol+0][arow] = a0.x; As[acol+1][arow] = a0.y;
        As[acol+2][arow] = a0.z; As[acol+3][arow] = a0.w;
        As[acol+0][arow+64] = a1.x; As[acol+1][arow+64] = a1.y;
        As[acol+2][arow+64] = a1.z; As[acol+3][arow+64] = a1.w;

        if (TB) {
            float4 b0 = *(const float4*)(Bb + (long)arow * K + k0 + acol);
            float4 b1 = *(const float4*)(Bb + (long)(arow + 64) * K + k0 + acol);
            Bs[acol+0][arow] = b0.x; Bs[acol+1][arow] = b0.y;
            Bs[acol+2][arow] = b0.z; Bs[acol+3][arow] = b0.w;
            Bs[acol+0][arow+64] = b1.x; Bs[acol+1][arow+64] = b1.y;
            Bs[acol+2][arow+64] = b1.z; Bs[acol+3][arow+64] = b1.w;
        } else {
            float4 b0 = *(const float4*)(Bb + (long)(k0 + brow) * N + bcol);
            float4 b1 = *(const float4*)(Bb + (long)(k0 + brow + 8) * N + bcol);
            *(float4*)&Bs[brow][bcol]     = b0;
            *(float4*)&Bs[brow + 8][bcol] = b1;
        }
        __syncthreads();

        #pragma unroll
        for (int kk = 0; kk < 16; kk++) {
            float a[8], b[8];
            #pragma unroll
            for (int i = 0; i < 4; i++) {
                a[i]     = As[kk][ty*4 + i];
                a[i + 4] = As[kk][ty*4 + 64 + i];
            }
            #pragma unroll
            for (int j = 0; j < 4; j++) {
                b[j]     = Bs[kk][tx*4 + j];
                b[j + 4] = Bs[kk][tx*4 + 64 + j];
            }
            #pragma unroll
            for (int i = 0; i < 8; i++)
                #pragma unroll
                for (int j = 0; j < 8; j++)
                    acc[i][j] = fmaf(a[i], b[j], acc[i][j]);
        }
        __syncthreads();
    }

    #pragma unroll
    for (int i = 0; i < 8; i++) {
        int r = ty * 4 + (i < 4 ? i : 60 + i);
        #pragma unroll
        for (int jj = 0; jj < 2; jj++) {
            int c = tx * 4 + jj * 64;
            float4 vout;
            float* vp = &vout.x;
            #pragma unroll
            for (int j = 0; j < 4; j++) {
                float val = alpha * acc[i][jj * 4 + j];
                if (bias) val += bias[bn * 128 + c + j];
                if (GELU) val = 0.5f * val * (1.f + erff(val * 0.70710678118654752f));
                if (Rb)   val += Rb[(long)r * N + c + j];
                vp[j] = val;
            }
            *(float4*)(Cb + (long)r * N + c) = vout;
        }
    }
}

// ---------------- launch ----------------
extern "C" void kernel_launch(void* const* d_in, const int* in_sizes, int n_in,
                              void* d_out, int out_size) {
    const float* x      = (const float*)d_in[0];
    const float* anw    = (const float*)d_in[1];
    const float* mnw    = (const float*)d_in[2];
    const float* wq     = (const float*)d_in[3];
    const float* bq     = (const float*)d_in[4];
    const float* wk     = (const float*)d_in[5];
    const float* bk     = (const float*)d_in[6];
    const float* wv     = (const float*)d_in[7];
    const float* bv     = (const float*)d_in[8];
    const float* wo     = (const float*)d_in[9];
    const float* bo     = (const float*)d_in[10];
    const float* w1     = (const float*)d_in[11];
    const float* b1     = (const float*)d_in[12];
    const float* w2     = (const float*)d_in[13];
    const float* b2     = (const float*)d_in[14];
    float* out = (float*)d_out;

    float *xn, *q, *k, *v, *sc, *attn, *x1, *h, *h1;
    cudaGetSymbolAddress((void**)&xn,   g_xn);
    cudaGetSymbolAddress((void**)&q,    g_q);
    cudaGetSymbolAddress((void**)&k,    g_k);
    cudaGetSymbolAddress((void**)&v,    g_v);
    cudaGetSymbolAddress((void**)&sc,   g_sc);
    cudaGetSymbolAddress((void**)&attn, g_attn);
    cudaGetSymbolAddress((void**)&x1,   g_x1);
    cudaGetSymbolAddress((void**)&h,    g_h);
    cudaGetSymbolAddress((void**)&h1,   g_h1);

    const long TD = (long)TLEN * DIM;
    const long TT = (long)TLEN * TLEN;

    // 1) xn = rmsnorm(x, attn_norm_w)
    rmsnorm_kernel<<<BT, 256>>>(x, anw, xn);

    // 2-4) q,k,v = xn @ W + b   (M=16384, N=1024, K=1024)
    dim3 gQKV(DIM/128, BT/128, 1);
    sgemm_kernel<false,false><<<gQKV, 256>>>(xn, wq, q, BT, DIM, DIM, 0,0,0, 1.f, bq, nullptr);
    sgemm_kernel<false,false><<<gQKV, 256>>>(xn, wk, k, BT, DIM, DIM, 0,0,0, 1.f, bk, nullptr);
    sgemm_kernel<false,false><<<gQKV, 256>>>(xn, wv, v, BT, DIM, DIM, 0,0,0, 1.f, bv, nullptr);

    // 5) scores = q @ k^T / 32   (per batch: 2048x2048x1024, NT)
    dim3 gSC(TLEN/128, TLEN/128, BATCH);
    sgemm_kernel<true,false><<<gSC, 256>>>(q, k, sc, TLEN, TLEN, DIM,
                                           TD, TD, TT, 0.03125f, nullptr, nullptr);

    // 6) causal softmax in-place
    softmax_causal_kernel<<<dim3(TLEN, BATCH), 256>>>(sc);

    // 7) attn = probs @ v   (per batch: 2048x1024x2048, NN)
    dim3 gPV(DIM/128, TLEN/128, BATCH);
    sgemm_kernel<false,false><<<gPV, 256>>>(sc, v, attn, TLEN, DIM, TLEN,
                                            TT, TD, TD, 1.f, nullptr, nullptr);

    // 8) x1 = x + attn @ wo + bo
    sgemm_kernel<false,false><<<gQKV, 256>>>(attn, wo, x1, BT, DIM, DIM, 0,0,0, 1.f, bo, x);

    // 9) h = rmsnorm(x1, mlp_norm_w)
    rmsnorm_kernel<<<BT, 256>>>(x1, mnw, h);

    // 10) h1 = gelu(h @ w1 + b1)   (M=16384, N=4096, K=1024)
    dim3 gUP(HID/128, BT/128, 1);
    sgemm_kernel<false,true><<<gUP, 256>>>(h, w1, h1, BT, HID, DIM, 0,0,0, 1.f, b1, nullptr);

    // 11) out = x1 + h1 @ w2 + b2  (M=16384, N=1024, K=4096)
    dim3 gDN(DIM/128, BT/128, 1);
    sgemm_kernel<false,false><<<gDN, 256>>>(h1, w2, out, BT, DIM, HID, 0,0,0, 1.f, b2, x1);
}

// round 4
// speedup vs baseline: 3.5928x; 3.5928x over previous
#include <cuda_runtime.h>
#include <cstdint>
#include <math.h>

#define BATCH 8
#define TLEN  2048
#define DIM   1024
#define HID   4096
#define BT    (BATCH*TLEN)

// ---------------- scratch (device globals; allocation-free) ----------------
__device__ float g_xn  [(size_t)BT*DIM];
__device__ float g_q   [(size_t)BT*DIM];
__device__ float g_k   [(size_t)BT*DIM];
__device__ float g_v   [(size_t)BT*DIM];
__device__ float g_vT  [(size_t)BT*DIM];
__device__ float g_sc  [(size_t)BATCH*TLEN*TLEN];
__device__ float g_attn[(size_t)BT*DIM];
__device__ float g_x1  [(size_t)BT*DIM];
__device__ float g_h   [(size_t)BT*DIM];
__device__ float g_h1  [(size_t)BT*HID];
__device__ float g_wqT [(size_t)DIM*DIM];
__device__ float g_wkT [(size_t)DIM*DIM];
__device__ float g_wvT [(size_t)DIM*DIM];
__device__ float g_woT [(size_t)DIM*DIM];
__device__ float g_w1T [(size_t)DIM*HID];
__device__ float g_w2T [(size_t)DIM*HID];

// ---------------- helpers ----------------
__device__ __forceinline__ uint32_t smem_u32(const void* p) {
    uint32_t a;
    asm("{ .reg .u64 t; cvta.to.shared.u64 t, %1; cvt.u32.u64 %0, t; }" : "=r"(a) : "l"(p));
    return a;
}
__device__ __forceinline__ float to_tf32(float x) {
    uint32_t u;
    asm("cvt.rna.tf32.f32 %0, %1;" : "=r"(u) : "f"(x));
    return __uint_as_float(u);
}
#define CPA(dst, src) \
    asm volatile("cp.async.cg.shared.global [%0], [%1], 16;" :: "r"(dst), "l"(src) : "memory")
#define CPA_COMMIT() asm volatile("cp.async.commit_group;" ::: "memory")
#define CPA_WAIT1()  asm volatile("cp.async.wait_group 1;" ::: "memory")

__device__ __forceinline__ void mma_tf32(float* d, const uint32_t* a, const uint32_t* b) {
    asm volatile(
        "mma.sync.aligned.m16n8k8.row.col.f32.tf32.tf32.f32 "
        "{%0,%1,%2,%3}, {%4,%5,%6,%7}, {%8,%9}, {%0,%1,%2,%3};"
        : "+f"(d[0]), "+f"(d[1]), "+f"(d[2]), "+f"(d[3])
        : "r"(a[0]), "r"(a[1]), "r"(a[2]), "r"(a[3]), "r"(b[0]), "r"(b[1]));
}

// ---------------- tf32 MMA GEMM: C = alpha*(A @ B^T) [+bias] [gelu] [+res] ----
// A: [M x K] row-major. B: [N x K] row-major. Tile 128x128x32, 256 thr, 8 warps.
// flags: 1 = skip tiles bn>bm (causal scores), 2 = clamp K to (bm+1)*128 (PV).
#define SROW 36
#define STAGE_F (128 * SROW)
#define SMEM_BYTES (2 * 2 * STAGE_F * 4)

template<bool GELU, bool CVT>
__global__ void __launch_bounds__(256, 2) mma_gemm(
    const float* __restrict__ A, const float* __restrict__ B, float* __restrict__ C,
    int K, int lda, int ldb, int ldc,
    long sA, long sB, long sC,
    float alpha, const float* __restrict__ bias, const float* __restrict__ res,
    int flags)
{
    int bn = blockIdx.x, bm = blockIdx.y, bz = blockIdx.z;
    if ((flags & 1) && bn > bm) return;
    int Keff = (flags & 2) ? min(K, (bm + 1) * 128) : K;

    extern __shared__ float smf[];
    float* As = smf;
    float* Bs = smf + 2 * STAGE_F;
    uint32_t asb = smem_u32(As), bsb = smem_u32(Bs);

    int tid = threadIdx.x;
    int lane = tid & 31, warp = tid >> 5;
    int wm = warp & 3, wn = warp >> 2;
    int m0 = wm * 32, n0 = wn * 64;
    int lq = lane >> 2, lr = lane & 3;

    const float* Ab = A + (long)bz * sA + (long)bm * 128 * lda;
    const float* Bb = B + (long)bz * sB + (long)bn * 128 * ldb;

    int lc = (tid & 7) * 4;   // float offset of 16B chunk within 32-float k-slab
    int mr = tid >> 3;        // 0..31

    float acc[2][8][4];
    #pragma unroll
    for (int mt = 0; mt < 2; mt++)
        #pragma unroll
        for (int nt = 0; nt < 8; nt++)
            #pragma unroll
            for (int r = 0; r < 4; r++) acc[mt][nt][r] = 0.f;

    int nk = Keff >> 5;

    // ---- loads for one stage ----
    #define LOAD_STAGE(st, k0)                                                  \
        {                                                                       \
            _Pragma("unroll")                                                   \
            for (int i = 0; i < 4; i++) {                                       \
                int m = mr + i * 32;                                            \
                uint32_t da = asb + (uint32_t)(((st) * 128 + m) * SROW + lc) * 4; \
                uint32_t db = bsb + (uint32_t)(((st) * 128 + m) * SROW + lc) * 4; \
                CPA(da, Ab + (long)m * lda + (k0) + lc);                        \
                CPA(db, Bb + (long)m * ldb + (k0) + lc);                        \
            }                                                                   \
            CPA_COMMIT();                                                       \
        }

    LOAD_STAGE(0, 0)
    if (nk > 1) LOAD_STAGE(1, 32)
    else CPA_COMMIT();   // keep group count consistent

    for (int i = 0; i < nk; i++) {
        int s = i & 1;
        CPA_WAIT1();
        __syncthreads();

        const float* Ash = As + s * STAGE_F;
        const float* Bsh = Bs + s * STAGE_F;
        #pragma unroll
        for (int ks = 0; ks < 4; ks++) {
            int kk = ks * 8 + lr;
            uint32_t a[2][4];
            #pragma unroll
            for (int mt = 0; mt < 2; mt++) {
                const float* p = Ash + (m0 + mt * 16 + lq) * SROW + kk;
                a[mt][0] = __float_as_uint(p[0]);
                a[mt][1] = __float_as_uint(p[8 * SROW]);
                a[mt][2] = __float_as_uint(p[4]);
                a[mt][3] = __float_as_uint(p[8 * SROW + 4]);
            }
            #pragma unroll
            for (int nt = 0; nt < 8; nt++) {
                const float* pb = Bsh + (n0 + nt * 8 + lq) * SROW + kk;
                uint32_t b[2];
                b[0] = __float_as_uint(pb[0]);
                b[1] = __float_as_uint(pb[4]);
                #pragma unroll
                for (int mt = 0; mt < 2; mt++)
                    mma_tf32(acc[mt][nt], a[mt], b);
            }
        }
        __syncthreads();
        if (i + 2 < nk) {
            int k0 = (i + 2) * 32;
            LOAD_STAGE(s, k0)
        } else {
            CPA_COMMIT();
        }
    }

    // ---- epilogue ----
    #pragma unroll
    for (int mt = 0; mt < 2; mt++) {
        int r1 = bm * 128 + m0 + mt * 16 + lq;
        #pragma unroll
        for (int half = 0; half < 2; half++) {
            int r = r1 + half * 8;
            float* Cp = C + (long)bz * sC + (long)r * ldc + bn * 128;
            const float* Rp = res ? (res + (long)bz * sC + (long)r * ldc + bn * 128) : nullptr;
            #pragma unroll
            for (int nt = 0; nt < 8; nt++) {
                int cc = n0 + nt * 8 + lr * 2;
                float2 o;
                #pragma unroll
                for (int j = 0; j < 2; j++) {
                    float val = alpha * acc[mt][nt][half * 2 + j];
                    if (bias) val += __ldg(&bias[bn * 128 + cc + j]);
                    if (GELU) val = 0.5f * val * (1.f + erff(val * 0.70710678118654752f));
                    if (Rp)   val += Rp[cc + j];
                    if (CVT)  val = to_tf32(val);
                    (&o.x)[j] = val;
                }
                *(float2*)(Cp + cc) = o;
            }
        }
    }
}

// ---------------- transpose (+ tf32 cvt): dst[C][R] = src[R][C] ----------------
__global__ void transpose_kernel(const float* __restrict__ src, float* __restrict__ dst,
                                 int R, int C, long sS, long sD) {
    __shared__ float t[32][33];
    int c0 = blockIdx.x * 32, r0 = blockIdx.y * 32;
    const float* s = src + (long)blockIdx.z * sS;
    float* d = dst + (long)blockIdx.z * sD;
    int x = threadIdx.x, y = threadIdx.y;
    #pragma unroll
    for (int i = 0; i < 32; i += 8) t[y + i][x] = s[(long)(r0 + y + i) * C + c0 + x];
    __syncthreads();
    #pragma unroll
    for (int i = 0; i < 32; i += 8) d[(long)(c0 + y + i) * R + r0 + x] = to_tf32(t[x][y + i]);
}

// ---------------- RMSNorm (+ tf32 cvt on output) ----------------
__global__ void rmsnorm_kernel(const float* __restrict__ x,
                               const float* __restrict__ w,
                               float* __restrict__ o) {
    int row = blockIdx.x;
    int tid = threadIdx.x;
    const float4* xr = (const float4*)(x + (size_t)row * DIM);
    float4 v = xr[tid];
    float ss = v.x*v.x + v.y*v.y + v.z*v.z + v.w*v.w;
    #pragma unroll
    for (int off = 16; off; off >>= 1) ss += __shfl_xor_sync(~0u, ss, off);
    __shared__ float red[8];
    if ((tid & 31) == 0) red[tid >> 5] = ss;
    __syncthreads();
    float tot = 0.f;
    #pragma unroll
    for (int i = 0; i < 8; i++) tot += red[i];
    float inv = rsqrtf(tot * (1.0f/DIM) + 1e-6f);
    float4 w4 = ((const float4*)w)[tid];
    float4 r;
    r.x = to_tf32(v.x * inv * w4.x); r.y = to_tf32(v.y * inv * w4.y);
    r.z = to_tf32(v.z * inv * w4.z); r.w = to_tf32(v.w * inv * w4.w);
    ((float4*)(o + (size_t)row * DIM))[tid] = r;
}

// ---------------- causal softmax (in-place, + tf32 cvt on probs) ----------------
__global__ void softmax_causal_kernel(float* __restrict__ s) {
    int t = blockIdx.x;
    int b = blockIdx.y;
    float* row = s + ((size_t)b * TLEN + t) * TLEN;
    int tid = threadIdx.x;
    int nvalid = t + 1;
    float vals[8];
    float mx = -3.0e38f;
    #pragma unroll
    for (int i = 0; i < 8; i++) {
        int idx = tid + i * 256;
        vals[i] = (idx < nvalid) ? row[idx] : -3.0e38f;
        mx = fmaxf(mx, vals[i]);
    }
    __shared__ float red[8];
    #pragma unroll
    for (int off = 16; off; off >>= 1) mx = fmaxf(mx, __shfl_xor_sync(~0u, mx, off));
    if ((tid & 31) == 0) red[tid >> 5] = mx;
    __syncthreads();
    mx = -3.0e38f;
    #pragma unroll
    for (int i = 0; i < 8; i++) mx = fmaxf(mx, red[i]);

    float sum = 0.f;
    #pragma unroll
    for (int i = 0; i < 8; i++) {
        int idx = tid + i * 256;
        vals[i] = (idx < nvalid) ? __expf(vals[i] - mx) : 0.f;
        sum += vals[i];
    }
    #pragma unroll
    for (int off = 16; off; off >>= 1) sum += __shfl_xor_sync(~0u, sum, off);
    __syncthreads();
    if ((tid & 31) == 0) red[tid >> 5] = sum;
    __syncthreads();
    float tot = 0.f;
    #pragma unroll
    for (int i = 0; i < 8; i++) tot += red[i];
    float inv = 1.0f / tot;
    #pragma unroll
    for (int i = 0; i < 8; i++) {
        int idx = tid + i * 256;
        row[idx] = to_tf32(vals[i] * inv);
    }
}

// ---------------- launch ----------------
extern "C" void kernel_launch(void* const* d_in, const int* in_sizes, int n_in,
                              void* d_out, int out_size) {
    const float* x   = (const float*)d_in[0];
    const float* anw = (const float*)d_in[1];
    const float* mnw = (const float*)d_in[2];
    const float* wq  = (const float*)d_in[3];
    const float* bq  = (const float*)d_in[4];
    const float* wk  = (const float*)d_in[5];
    const float* bk  = (const float*)d_in[6];
    const float* wv  = (const float*)d_in[7];
    const float* bv  = (const float*)d_in[8];
    const float* wo  = (const float*)d_in[9];
    const float* bo  = (const float*)d_in[10];
    const float* w1  = (const float*)d_in[11];
    const float* b1  = (const float*)d_in[12];
    const float* w2  = (const float*)d_in[13];
    const float* b2  = (const float*)d_in[14];
    float* out = (float*)d_out;

    float *xn, *q, *k, *v, *vT, *sc, *attn, *x1, *h, *h1;
    float *wqT, *wkT, *wvT, *woT, *w1T, *w2T;
    cudaGetSymbolAddress((void**)&xn,   g_xn);
    cudaGetSymbolAddress((void**)&q,    g_q);
    cudaGetSymbolAddress((void**)&k,    g_k);
    cudaGetSymbolAddress((void**)&v,    g_v);
    cudaGetSymbolAddress((void**)&vT,   g_vT);
    cudaGetSymbolAddress((void**)&sc,   g_sc);
    cudaGetSymbolAddress((void**)&attn, g_attn);
    cudaGetSymbolAddress((void**)&x1,   g_x1);
    cudaGetSymbolAddress((void**)&h,    g_h);
    cudaGetSymbolAddress((void**)&h1,   g_h1);
    cudaGetSymbolAddress((void**)&wqT,  g_wqT);
    cudaGetSymbolAddress((void**)&wkT,  g_wkT);
    cudaGetSymbolAddress((void**)&wvT,  g_wvT);
    cudaGetSymbolAddress((void**)&woT,  g_woT);
    cudaGetSymbolAddress((void**)&w1T,  g_w1T);
    cudaGetSymbolAddress((void**)&w2T,  g_w2T);

    cudaFuncSetAttribute(mma_gemm<false,false>, cudaFuncAttributeMaxDynamicSharedMemorySize, SMEM_BYTES);
    cudaFuncSetAttribute(mma_gemm<false,true>,  cudaFuncAttributeMaxDynamicSharedMemorySize, SMEM_BYTES);
    cudaFuncSetAttribute(mma_gemm<true,true>,   cudaFuncAttributeMaxDynamicSharedMemorySize, SMEM_BYTES);

    const long TD = (long)TLEN * DIM;
    const long TT = (long)TLEN * TLEN;
    dim3 tb(32, 8);

    // weight transposes (convert to tf32)
    transpose_kernel<<<dim3(32, 32), tb>>>(wq, wqT, DIM, DIM, 0, 0);
    transpose_kernel<<<dim3(32, 32), tb>>>(wk, wkT, DIM, DIM, 0, 0);
    transpose_kernel<<<dim3(32, 32), tb>>>(wv, wvT, DIM, DIM, 0, 0);
    transpose_kernel<<<dim3(32, 32), tb>>>(wo, woT, DIM, DIM, 0, 0);
    transpose_kernel<<<dim3(128, 32), tb>>>(w1, w1T, DIM, HID, 0, 0);
    transpose_kernel<<<dim3(32, 128), tb>>>(w2, w2T, HID, DIM, 0, 0);

    // 1) xn = rmsnorm(x) (tf32)
    rmsnorm_kernel<<<BT, 256>>>(x, anw, xn);

    // 2-4) q,k,v = xn @ W^T + b  (q,k emitted as tf32; v stays fp32, cvt at transpose)
    dim3 gQKV(DIM / 128, BT / 128, 1);
    mma_gemm<false,true> <<<gQKV, 256, SMEM_BYTES>>>(xn, wqT, q, DIM, DIM, DIM, DIM, 0,0,0, 1.f, bq, nullptr, 0);
    mma_gemm<false,true> <<<gQKV, 256, SMEM_BYTES>>>(xn, wkT, k, DIM, DIM, DIM, DIM, 0,0,0, 1.f, bk, nullptr, 0);
    mma_gemm<false,false><<<gQKV, 256, SMEM_BYTES>>>(xn, wvT, v, DIM, DIM, DIM, DIM, 0,0,0, 1.f, bv, nullptr, 0);

    // v^T per batch: [T,D] -> [D,T] (tf32)
    transpose_kernel<<<dim3(DIM / 32, TLEN / 32, BATCH), tb>>>(v, vT, TLEN, DIM, TD, TD);

    // 5) scores = q @ k^T / 32, causal tiles only
    dim3 gSC(TLEN / 128, TLEN / 128, BATCH);
    mma_gemm<false,false><<<gSC, 256, SMEM_BYTES>>>(q, k, sc, DIM, DIM, DIM, TLEN,
                                                    TD, TD, TT, 0.03125f, nullptr, nullptr, 1);

    // 6) causal softmax (probs emitted as tf32)
    softmax_causal_kernel<<<dim3(TLEN, BATCH), 256>>>(sc);

    // 7) attn = probs @ v  (B = vT, K clamped causally; attn emitted tf32)
    dim3 gPV(DIM / 128, TLEN / 128, BATCH);
    mma_gemm<false,true><<<gPV, 256, SMEM_BYTES>>>(sc, vT, attn, TLEN, TLEN, TLEN, DIM,
                                                   TT, TD, TD, 1.f, nullptr, nullptr, 2);

    // 8) x1 = x + attn @ wo^T + bo   (fp32 out)
    mma_gemm<false,false><<<gQKV, 256, SMEM_BYTES>>>(attn, woT, x1, DIM, DIM, DIM, DIM, 0,0,0, 1.f, bo, x, 0);

    // 9) h = rmsnorm(x1) (tf32)
    rmsnorm_kernel<<<BT, 256>>>(x1, mnw, h);

    // 10) h1 = gelu(h @ w1^T + b1) (tf32 out)
    dim3 gUP(HID / 128, BT / 128, 1);
    mma_gemm<true,true><<<gUP, 256, SMEM_BYTES>>>(h, w1T, h1, DIM, DIM, DIM, HID, 0,0,0, 1.f, b1, nullptr, 0);

    // 11) out = x1 + h1 @ w2^T + b2 (fp32 out)
    dim3 gDN(DIM / 128, BT / 128, 1);
    mma_gemm<false,false><<<gDN, 256, SMEM_BYTES>>>(h1, w2T, out, HID, HID, HID, DIM, 0,0,0, 1.f, b2, x1, 0);
}